// round 10
// baseline (speedup 1.0000x reference)
#include <cuda_runtime.h>
#include <cuda_bf16.h>
#include <cstdint>

#define BB 512
#define LL 512
#define NN 128

__device__ float g_norm[BB];
__device__ float g_path[BB];

__device__ __forceinline__ uint32_t bfpack(float lo, float hi) {
    uint32_t d;
    asm("cvt.rn.bf16x2.f32 %0, %1, %2;" : "=r"(d) : "f"(hi), "f"(lo));
    return d;
}
__device__ __forceinline__ float frcp(float x) {
    float r;
    asm("rcp.approx.f32 %0, %1;" : "=f"(r) : "f"(x));
    return r;
}
__device__ __forceinline__ uint32_t movm(uint32_t x) {
    uint32_t d;
    asm("movmatrix.sync.aligned.m8n8.trans.b16 %0, %1;" : "=r"(d) : "r"(x));
    return d;
}
__device__ __forceinline__ void mma16816(float* d,
                                         uint32_t a0, uint32_t a1, uint32_t a2, uint32_t a3,
                                         uint32_t b0, uint32_t b1) {
    asm volatile("mma.sync.aligned.m16n8k16.row.col.f32.bf16.bf16.f32 "
                 "{%0,%1,%2,%3},{%4,%5,%6,%7},{%8,%9},{%0,%1,%2,%3};"
                 : "+f"(d[0]), "+f"(d[1]), "+f"(d[2]), "+f"(d[3])
                 : "r"(a0), "r"(a1), "r"(a2), "r"(a3), "r"(b0), "r"(b1));
}
__device__ __forceinline__ float blendq(float mk, float qc, float qold_inv) {
    if (mk == 1.0f) return qc;
    if (mk == 0.0f) return qold_inv;
    return __expf(mk * __logf(qc) + (1.0f - mk) * __logf(qold_inv));
}

// ---------------------------------------------------------------------------
// Forward: 64 blocks x 64 threads (2 warps). Block = 8 batches, ZERO padding.
// C[128 states x 8 batches] = E^T[128x128] @ q[128 x 8]; warp w owns m-tiles
// 4w..4w+3 (output states 64w..64w+63); A = E^T fragments resident (128 regs).
// Next-step B fragments produced in registers via movmatrix on scaled C.
// Linear-domain recurrence (stale-q0 shift); one __syncthreads per step.
// ---------------------------------------------------------------------------
__global__ __launch_bounds__(64, 1)
void crf_forward(const float* __restrict__ em,
                 const float* __restrict__ mask,
                 const float* __restrict__ start,
                 const float* __restrict__ trans) {
    __shared__ uint2 qfr[2][8][32];    // [parity][k-tile][lane] = (b0,b1)
    __shared__ float invsh[2][8];      // [parity][batch] = 1/q_{t-1}[0]
    __shared__ float csh[8];
    __shared__ float ssum[2][8];

    const int tid  = threadIdx.x;
    const int w    = tid >> 5;
    const int lane = tid & 31;
    const int r    = lane >> 2;        // frag row within 8-block
    const int c    = lane & 3;
    const int bA   = 2 * c, bB = bA + 1;   // this thread's 2 batches (C cols)
    const int b0g  = blockIdx.x * 8;

    // this thread's 8 output states: [m][row] = 16*(4w+m) + r (+8)
    int S[4][2];
#pragma unroll
    for (int m = 0; m < 4; m++) { S[m][0] = 16 * (4 * w + m) + r; S[m][1] = S[m][0] + 8; }

    // ---- A fragments: A[j][i] = E[i][j] = exp(trans[i*128+j]), resident ----
    uint32_t Af[4][8][4];
#pragma unroll
    for (int m = 0; m < 4; m++) {
        const int j0 = S[m][0], j1 = S[m][1];
#pragma unroll
        for (int kt = 0; kt < 8; kt++) {
            const int i0 = 16 * kt + 2 * c;
            Af[m][kt][0] = bfpack(__expf(trans[(i0)     * NN + j0]),
                                  __expf(trans[(i0 + 1) * NN + j0]));
            Af[m][kt][1] = bfpack(__expf(trans[(i0)     * NN + j1]),
                                  __expf(trans[(i0 + 1) * NN + j1]));
            Af[m][kt][2] = bfpack(__expf(trans[(i0 + 8) * NN + j0]),
                                  __expf(trans[(i0 + 9) * NN + j0]));
            Af[m][kt][3] = bfpack(__expf(trans[(i0 + 8) * NN + j1]),
                                  __expf(trans[(i0 + 9) * NN + j1]));
        }
    }

    const float* emA = em + (size_t)(b0g + bA) * (LL * NN);
    const float* emB = em + (size_t)(b0g + bB) * (LL * NN);
    const float* mkAp = mask + (size_t)(b0g + bA) * LL;
    const float* mkBp = mask + (size_t)(b0g + bB) * LL;

    float LrA = 0.f, LrB = 0.f;          // log-offsets (writer lanes only)
    float qprev[4][2][2];                // q_{t-1} in C layout [m][row][batch]

    // ---- init t=0 ----
    {
        float sA[4][2], sB[4][2];
#pragma unroll
        for (int m = 0; m < 4; m++)
#pragma unroll
            for (int row = 0; row < 2; row++) {
                const int s = S[m][row];
                const float st = start[s];
                sA[m][row] = st + emA[s];
                sB[m][row] = st + emB[s];
            }
        if (w == 0 && r == 0) { csh[bA] = sA[0][0]; csh[bB] = sB[0][0]; }
        __syncthreads();
        const float cA_ = csh[bA], cB_ = csh[bB];
        LrA = cA_; LrB = cB_;
#pragma unroll
        for (int m = 0; m < 4; m++)
#pragma unroll
            for (int row = 0; row < 2; row++) {
                qprev[m][row][0] = __expf(sA[m][row] - cA_);
                qprev[m][row][1] = __expf(sB[m][row] - cB_);
            }
        if (w == 0 && r == 0) {
            invsh[1][bA] = frcp(qprev[0][0][0]);
            invsh[1][bB] = frcp(qprev[0][0][1]);
        }
#pragma unroll
        for (int m = 0; m < 4; m++) {
            const int kt = 4 * w + m;
            uint32_t u0 = bfpack(qprev[m][0][0], qprev[m][0][1]);
            uint32_t u1 = bfpack(qprev[m][1][0], qprev[m][1][1]);
            qfr[1][kt][lane] = make_uint2(movm(u0), movm(u1));
        }
    }

    // ---- prefetch t=1: exp(emission) + mask ----
    float et[4][2][2];
#pragma unroll
    for (int m = 0; m < 4; m++)
#pragma unroll
        for (int row = 0; row < 2; row++) {
            et[m][row][0] = __expf(emA[NN + S[m][row]]);
            et[m][row][1] = __expf(emB[NN + S[m][row]]);
        }
    float mkA = mkAp[1], mkB = mkBp[1];
    __syncthreads();

    for (int t = 1; t < LL; t++) {
        const int pr = t & 1, pw = pr ^ 1;

        // ---- load B frags + inv (written last step) ----
        uint2 bq[8];
#pragma unroll
        for (int kt = 0; kt < 8; kt++) bq[kt] = qfr[pr][kt][lane];
        const float invA = invsh[pr][bA];
        const float invB = invsh[pr][bB];

        // ---- prefetch em(t+1), mask(t+1) ----
        float emn[4][2][2];
        float mknA = 1.0f, mknB = 1.0f;
        if (t + 1 < LL) {
            const int off = (t + 1) * NN;
#pragma unroll
            for (int m = 0; m < 4; m++)
#pragma unroll
                for (int row = 0; row < 2; row++) {
                    emn[m][row][0] = emA[off + S[m][row]];
                    emn[m][row][1] = emB[off + S[m][row]];
                }
            mknA = mkAp[t + 1]; mknB = mkBp[t + 1];
        } else {
#pragma unroll
            for (int m = 0; m < 4; m++)
#pragma unroll
                for (int row = 0; row < 2; row++)
                    emn[m][row][0] = emn[m][row][1] = 0.0f;
        }

        // ---- MMA: C = E^T @ q ; 4 independent chains of depth 8 ----
        float C_[4][4];
#pragma unroll
        for (int m = 0; m < 4; m++)
#pragma unroll
            for (int i = 0; i < 4; i++) C_[m][i] = 0.0f;
#pragma unroll
        for (int kt = 0; kt < 8; kt++) {
#pragma unroll
            for (int m = 0; m < 4; m++)
                mma16816(C_[m], Af[m][kt][0], Af[m][kt][1], Af[m][kt][2], Af[m][kt][3],
                         bq[kt].x, bq[kt].y);
        }

        // ---- epilogue: scale, mask-blend, recycle into B frags ----
        float qn[4][2][2];
#pragma unroll
        for (int m = 0; m < 4; m++) {
            float qcA0 = C_[m][0] * et[m][0][0] * invA;
            float qcB0 = C_[m][1] * et[m][0][1] * invB;
            float qcA1 = C_[m][2] * et[m][1][0] * invA;
            float qcB1 = C_[m][3] * et[m][1][1] * invB;
            qn[m][0][0] = blendq(mkA, qcA0, qprev[m][0][0] * invA);
            qn[m][0][1] = blendq(mkB, qcB0, qprev[m][0][1] * invB);
            qn[m][1][0] = blendq(mkA, qcA1, qprev[m][1][0] * invA);
            qn[m][1][1] = blendq(mkB, qcB1, qprev[m][1][1] * invB);
        }
        if (w == 0 && r == 0) {
            LrA -= __logf(invA);
            LrB -= __logf(invB);
            invsh[pw][bA] = frcp(qn[0][0][0]);
            invsh[pw][bB] = frcp(qn[0][0][1]);
        }
#pragma unroll
        for (int m = 0; m < 4; m++) {
#pragma unroll
            for (int row = 0; row < 2; row++) {
                qprev[m][row][0] = qn[m][row][0];
                qprev[m][row][1] = qn[m][row][1];
            }
            const int kt = 4 * w + m;
            uint32_t u0 = bfpack(qn[m][0][0], qn[m][0][1]);
            uint32_t u1 = bfpack(qn[m][1][0], qn[m][1][1]);
            qfr[pw][kt][lane] = make_uint2(movm(u0), movm(u1));
        }

        // ---- exps for t+1 (MUFU, off the critical path) ----
#pragma unroll
        for (int m = 0; m < 4; m++)
#pragma unroll
            for (int row = 0; row < 2; row++) {
                et[m][row][0] = __expf(emn[m][row][0]);
                et[m][row][1] = __expf(emn[m][row][1]);
            }
        mkA = mknA; mkB = mknB;
        __syncthreads();
    }

    // ---- final: normalizer[b] = L[b] + log(sum_states q) ----
    float sA = 0.f, sB = 0.f;
#pragma unroll
    for (int m = 0; m < 4; m++)
#pragma unroll
        for (int row = 0; row < 2; row++) { sA += qprev[m][row][0]; sB += qprev[m][row][1]; }
#pragma unroll
    for (int o = 4; o <= 16; o <<= 1) {
        sA += __shfl_xor_sync(0xffffffffu, sA, o);
        sB += __shfl_xor_sync(0xffffffffu, sB, o);
    }
    if (r == 0) { ssum[w][bA] = sA; ssum[w][bB] = sB; }
    __syncthreads();
    if (w == 0 && r == 0) {
        g_norm[b0g + bA] = LrA + __logf(ssum[0][bA] + ssum[1][bA]);
        g_norm[b0g + bB] = LrB + __logf(ssum[0][bB] + ssum[1][bB]);
    }
}

// ---------------------------------------------------------------------------
// Path score. One block (128 threads) per batch.
// ---------------------------------------------------------------------------
__global__ __launch_bounds__(128)
void crf_path(const float* __restrict__ em,
              const int*   __restrict__ tgt,
              const float* __restrict__ mask,
              const float* __restrict__ start,
              const float* __restrict__ trans) {
    const int bb = blockIdx.x;
    const int tid = threadIdx.x;
    __shared__ float red[128];

    const size_t embase = (size_t)bb * LL * NN;
    float s = 0.0f;
    for (int t = tid; t < LL; t += 128) {
        if (t == 0) {
            int t0 = tgt[bb * LL];
            s += start[t0] + em[embase + t0];
        } else {
            int prev = tgt[bb * LL + t - 1];
            int cur  = tgt[bb * LL + t];
            s += mask[bb * LL + t] *
                 (trans[prev * NN + cur] + em[embase + (size_t)t * NN + cur]);
        }
    }
    red[tid] = s;
    __syncthreads();
#pragma unroll
    for (int o = 64; o; o >>= 1) {
        if (tid < o) red[tid] += red[tid + o];
        __syncthreads();
    }
    if (tid == 0) g_path[bb] = red[0];
}

// ---------------------------------------------------------------------------
// mean(normalizer - path)
// ---------------------------------------------------------------------------
__global__ __launch_bounds__(512)
void crf_final(float* __restrict__ out) {
    const int tid = threadIdx.x;
    __shared__ float wsum[16];
    float v = g_norm[tid] - g_path[tid];
#pragma unroll
    for (int o = 16; o; o >>= 1) v += __shfl_xor_sync(0xffffffffu, v, o);
    if ((tid & 31) == 0) wsum[tid >> 5] = v;
    __syncthreads();
    if (tid < 32) {
        float x = (tid < 16) ? wsum[tid] : 0.0f;
#pragma unroll
        for (int o = 8; o; o >>= 1) x += __shfl_xor_sync(0xffffffffu, x, o);
        if (tid == 0) out[0] = x * (1.0f / (float)BB);
    }
}

// ---------------------------------------------------------------------------
// Launch
// ---------------------------------------------------------------------------
extern "C" void kernel_launch(void* const* d_in, const int* in_sizes, int n_in,
                              void* d_out, int out_size) {
    const float* emission    = (const float*)d_in[0];
    const int*   target      = (const int*)  d_in[1];
    const float* mask        = (const float*)d_in[2];
    const float* start_trans = (const float*)d_in[3];
    const float* trans       = (const float*)d_in[4];
    float* out = (float*)d_out;

    crf_forward<<<64, 64>>>(emission, mask, start_trans, trans);
    crf_path<<<BB, 128>>>(emission, target, mask, start_trans, trans);
    crf_final<<<1, 512>>>(out);
}

// round 11
// speedup vs baseline: 1.8778x; 1.8778x over previous
#include <cuda_runtime.h>
#include <cuda_bf16.h>
#include <cstdint>

#define BB 512
#define LL 512
#define NN 128
#define EPITCH 132   // padded emission-stage pitch (floats)

__device__ float g_norm[BB];
__device__ float g_path[BB];

__device__ __forceinline__ uint32_t bfpack(float lo, float hi) {
    uint32_t d;
    asm("cvt.rn.bf16x2.f32 %0, %1, %2;" : "=r"(d) : "f"(hi), "f"(lo));
    return d;
}
__device__ __forceinline__ float frcp(float x) {
    float r;
    asm("rcp.approx.f32 %0, %1;" : "=f"(r) : "f"(x));
    return r;
}
__device__ __forceinline__ uint32_t movm(uint32_t x) {
    uint32_t d;
    asm("movmatrix.sync.aligned.m8n8.trans.b16 %0, %1;" : "=r"(d) : "r"(x));
    return d;
}
__device__ __forceinline__ void mma16816(float* d,
                                         uint32_t a0, uint32_t a1, uint32_t a2, uint32_t a3,
                                         uint32_t b0, uint32_t b1) {
    asm volatile("mma.sync.aligned.m16n8k16.row.col.f32.bf16.bf16.f32 "
                 "{%0,%1,%2,%3},{%4,%5,%6,%7},{%8,%9},{%0,%1,%2,%3};"
                 : "+f"(d[0]), "+f"(d[1]), "+f"(d[2]), "+f"(d[3])
                 : "r"(a0), "r"(a1), "r"(a2), "r"(a3), "r"(b0), "r"(b1));
}
__device__ __forceinline__ float blendq(float mk, float qc, float qold_inv) {
    if (mk == 1.0f) return qc;
    if (mk == 0.0f) return qold_inv;
    return __expf(mk * __logf(qc) + (1.0f - mk) * __logf(qold_inv));
}

// ---------------------------------------------------------------------------
// Forward: 64 blocks x 128 threads (4 warps). Block = 8 batches, ZERO padding.
// C[128 states x 8 batches] = E^T @ q; warp w owns m-tiles {2w, 2w+1}
// (states 32w..32w+31): 16 HMMA/warp/step, A=E^T frags resident (64 regs).
// Next-step B frags produced in registers (movmatrix) and exchanged via smem.
// Emission staged one step ahead through smem (coalesced LDG, padded LDS).
// Linear-domain recurrence (stale-q0 shift); one __syncthreads per step.
// ---------------------------------------------------------------------------
__global__ __launch_bounds__(128, 1)
void crf_forward(const float* __restrict__ em,
                 const float* __restrict__ mask,
                 const float* __restrict__ start,
                 const float* __restrict__ trans) {
    __shared__ uint2 qfr[2][8][32];        // [parity][k-tile][lane]
    __shared__ float invsh[2][8];          // [parity][batch]
    __shared__ float esh[2][8][EPITCH];    // staged emission [parity][batch][state]
    __shared__ float msh[2][8];            // staged mask
    __shared__ float csh[8];
    __shared__ float ssum[4][8];

    const int tid  = threadIdx.x;
    const int w    = tid >> 5;             // warp 0..3 -> m-tiles 2w, 2w+1
    const int lane = tid & 31;
    const int r    = lane >> 2;
    const int c    = lane & 3;
    const int bA   = 2 * c, bB = bA + 1;   // this thread's 2 batches
    const int b0g  = blockIdx.x * 8;
    const bool wr  = (w == 0 && r == 0);   // writer lanes (state 0 holders)

    // this thread's states: S[mi][half] = 16*(2w+mi) + r + 8*half
    int S[2][2];
#pragma unroll
    for (int mi = 0; mi < 2; mi++) {
        S[mi][0] = 16 * (2 * w + mi) + r;
        S[mi][1] = S[mi][0] + 8;
    }

    // ---- A fragments: A[j][i] = exp(trans[i*128+j]), resident ----
    uint32_t Af[2][8][4];
#pragma unroll
    for (int mi = 0; mi < 2; mi++) {
        const int j0 = S[mi][0], j1 = S[mi][1];
#pragma unroll
        for (int kt = 0; kt < 8; kt++) {
            const int i0 = 16 * kt + 2 * c;
            Af[mi][kt][0] = bfpack(__expf(trans[(i0)     * NN + j0]),
                                   __expf(trans[(i0 + 1) * NN + j0]));
            Af[mi][kt][1] = bfpack(__expf(trans[(i0)     * NN + j1]),
                                   __expf(trans[(i0 + 1) * NN + j1]));
            Af[mi][kt][2] = bfpack(__expf(trans[(i0 + 8) * NN + j0]),
                                   __expf(trans[(i0 + 9) * NN + j0]));
            Af[mi][kt][3] = bfpack(__expf(trans[(i0 + 8) * NN + j1]),
                                   __expf(trans[(i0 + 9) * NN + j1]));
        }
    }

    const size_t ebA = (size_t)(b0g + bA) * (LL * NN);
    const size_t ebB = (size_t)(b0g + bB) * (LL * NN);

    // coalesced emission-stage role: batch lb, states ls*8..ls*8+7
    const int lb = tid >> 4, ls = (tid & 15) * 8;
    const float* eml = em + (size_t)(b0g + lb) * (LL * NN) + ls;

    float Lr_A = 0.f, Lr_B = 0.f;          // log offsets (writer lanes)
    float qprev[2][2][2];                  // [mi][half][batch]

    // ================= init t = 0 =================
    {
        float s0[2][2][2];
#pragma unroll
        for (int mi = 0; mi < 2; mi++)
#pragma unroll
            for (int h = 0; h < 2; h++) {
                const int s = S[mi][h];
                const float st = start[s];
                s0[mi][h][0] = st + em[ebA + s];
                s0[mi][h][1] = st + em[ebB + s];
            }
        if (wr) { csh[bA] = s0[0][0][0]; csh[bB] = s0[0][0][1]; }
        __syncthreads();
        const float cA = csh[bA], cB = csh[bB];
        Lr_A = cA; Lr_B = cB;
#pragma unroll
        for (int mi = 0; mi < 2; mi++)
#pragma unroll
            for (int h = 0; h < 2; h++) {
                qprev[mi][h][0] = __expf(s0[mi][h][0] - cA);
                qprev[mi][h][1] = __expf(s0[mi][h][1] - cB);
            }
        if (wr) {
            invsh[1][bA] = frcp(qprev[0][0][0]);
            invsh[1][bB] = frcp(qprev[0][0][1]);
        }
#pragma unroll
        for (int mi = 0; mi < 2; mi++) {
            uint32_t u0 = bfpack(qprev[mi][0][0], qprev[mi][0][1]);
            uint32_t u1 = bfpack(qprev[mi][1][0], qprev[mi][1][1]);
            qfr[1][2 * w + mi][lane] = make_uint2(movm(u0), movm(u1));
        }
        // stage em[1] + mask[1]
        float4 v0 = *(const float4*)&eml[1 * NN];
        float4 v1 = *(const float4*)&eml[1 * NN + 4];
        *(float4*)&esh[1][lb][ls]     = v0;
        *(float4*)&esh[1][lb][ls + 4] = v1;
        if (tid < 8) msh[1][tid] = mask[(size_t)(b0g + tid) * LL + 1];
        __syncthreads();
    }

    // ================= recurrence =================
    for (int t = 1; t < LL; t++) {
        const int pr = t & 1, pw = pr ^ 1;

        // ---- B frags + inv (written last step) ----
        uint2 bq[8];
#pragma unroll
        for (int kt = 0; kt < 8; kt++) bq[kt] = qfr[pr][kt][lane];
        const float invA = invsh[pr][bA];
        const float invB = invsh[pr][bB];
        const float mkA = msh[pr][bA];
        const float mkB = msh[pr][bB];

        // ---- LDG em[t+1] (coalesced) ----
        float4 v0 = make_float4(0.f, 0.f, 0.f, 0.f), v1 = v0;
        float mvn = 1.0f;
        if (t + 1 < LL) {
            v0 = *(const float4*)&eml[(size_t)(t + 1) * NN];
            v1 = *(const float4*)&eml[(size_t)(t + 1) * NN + 4];
            if (tid < 8) mvn = mask[(size_t)(b0g + tid) * LL + t + 1];
        }

        // ---- et = exp(em[t]) from smem stage (MUFU, pre-MMA) ----
        float et[2][2][2];
#pragma unroll
        for (int mi = 0; mi < 2; mi++)
#pragma unroll
            for (int h = 0; h < 2; h++) {
                et[mi][h][0] = __expf(esh[pr][bA][S[mi][h]]);
                et[mi][h][1] = __expf(esh[pr][bB][S[mi][h]]);
            }

        // ---- MMA: 2 chains of depth 8, 16 HMMA ----
        float C0[4] = {0.f, 0.f, 0.f, 0.f};
        float C1[4] = {0.f, 0.f, 0.f, 0.f};
#pragma unroll
        for (int kt = 0; kt < 8; kt++) {
            mma16816(C0, Af[0][kt][0], Af[0][kt][1], Af[0][kt][2], Af[0][kt][3],
                     bq[kt].x, bq[kt].y);
            mma16816(C1, Af[1][kt][0], Af[1][kt][1], Af[1][kt][2], Af[1][kt][3],
                     bq[kt].x, bq[kt].y);
        }

        // ---- epilogue: scale, blend, recycle ----
        float qn[2][2][2];
        qn[0][0][0] = blendq(mkA, C0[0] * et[0][0][0] * invA, qprev[0][0][0] * invA);
        qn[0][0][1] = blendq(mkB, C0[1] * et[0][0][1] * invB, qprev[0][0][1] * invB);
        qn[0][1][0] = blendq(mkA, C0[2] * et[0][1][0] * invA, qprev[0][1][0] * invA);
        qn[0][1][1] = blendq(mkB, C0[3] * et[0][1][1] * invB, qprev[0][1][1] * invB);
        qn[1][0][0] = blendq(mkA, C1[0] * et[1][0][0] * invA, qprev[1][0][0] * invA);
        qn[1][0][1] = blendq(mkB, C1[1] * et[1][0][1] * invB, qprev[1][0][1] * invB);
        qn[1][1][0] = blendq(mkA, C1[2] * et[1][1][0] * invA, qprev[1][1][0] * invA);
        qn[1][1][1] = blendq(mkB, C1[3] * et[1][1][1] * invB, qprev[1][1][1] * invB);

        if (wr) {
            Lr_A -= __logf(invA);
            Lr_B -= __logf(invB);
            invsh[pw][bA] = frcp(qn[0][0][0]);
            invsh[pw][bB] = frcp(qn[0][0][1]);
        }
#pragma unroll
        for (int mi = 0; mi < 2; mi++) {
            uint32_t u0 = bfpack(qn[mi][0][0], qn[mi][0][1]);
            uint32_t u1 = bfpack(qn[mi][1][0], qn[mi][1][1]);
            qfr[pw][2 * w + mi][lane] = make_uint2(movm(u0), movm(u1));
#pragma unroll
            for (int h = 0; h < 2; h++) {
                qprev[mi][h][0] = qn[mi][h][0];
                qprev[mi][h][1] = qn[mi][h][1];
            }
        }

        // ---- stage em[t+1] / mask[t+1] ----
        *(float4*)&esh[pw][lb][ls]     = v0;
        *(float4*)&esh[pw][lb][ls + 4] = v1;
        if (tid < 8) msh[pw][tid] = mvn;
        __syncthreads();
    }

    // ================= final logsumexp =================
    float sA = 0.f, sB = 0.f;
#pragma unroll
    for (int mi = 0; mi < 2; mi++)
#pragma unroll
        for (int h = 0; h < 2; h++) { sA += qprev[mi][h][0]; sB += qprev[mi][h][1]; }
#pragma unroll
    for (int o = 4; o <= 16; o <<= 1) {
        sA += __shfl_xor_sync(0xffffffffu, sA, o);
        sB += __shfl_xor_sync(0xffffffffu, sB, o);
    }
    if (r == 0) { ssum[w][bA] = sA; ssum[w][bB] = sB; }
    __syncthreads();
    if (wr) {
        float tA = ssum[0][bA] + ssum[1][bA] + ssum[2][bA] + ssum[3][bA];
        float tB = ssum[0][bB] + ssum[1][bB] + ssum[2][bB] + ssum[3][bB];
        g_norm[b0g + bA] = Lr_A + __logf(tA);
        g_norm[b0g + bB] = Lr_B + __logf(tB);
    }
}

// ---------------------------------------------------------------------------
// Path score. One block (128 threads) per batch.
// ---------------------------------------------------------------------------
__global__ __launch_bounds__(128)
void crf_path(const float* __restrict__ em,
              const int*   __restrict__ tgt,
              const float* __restrict__ mask,
              const float* __restrict__ start,
              const float* __restrict__ trans) {
    const int bb = blockIdx.x;
    const int tid = threadIdx.x;
    __shared__ float red[128];

    const size_t embase = (size_t)bb * LL * NN;
    float s = 0.0f;
    for (int t = tid; t < LL; t += 128) {
        if (t == 0) {
            int t0 = tgt[bb * LL];
            s += start[t0] + em[embase + t0];
        } else {
            int prev = tgt[bb * LL + t - 1];
            int cur  = tgt[bb * LL + t];
            s += mask[bb * LL + t] *
                 (trans[prev * NN + cur] + em[embase + (size_t)t * NN + cur]);
        }
    }
    red[tid] = s;
    __syncthreads();
#pragma unroll
    for (int o = 64; o; o >>= 1) {
        if (tid < o) red[tid] += red[tid + o];
        __syncthreads();
    }
    if (tid == 0) g_path[bb] = red[0];
}

// ---------------------------------------------------------------------------
// mean(normalizer - path)
// ---------------------------------------------------------------------------
__global__ __launch_bounds__(512)
void crf_final(float* __restrict__ out) {
    const int tid = threadIdx.x;
    __shared__ float wsum[16];
    float v = g_norm[tid] - g_path[tid];
#pragma unroll
    for (int o = 16; o; o >>= 1) v += __shfl_xor_sync(0xffffffffu, v, o);
    if ((tid & 31) == 0) wsum[tid >> 5] = v;
    __syncthreads();
    if (tid < 32) {
        float x = (tid < 16) ? wsum[tid] : 0.0f;
#pragma unroll
        for (int o = 8; o; o >>= 1) x += __shfl_xor_sync(0xffffffffu, x, o);
        if (tid == 0) out[0] = x * (1.0f / (float)BB);
    }
}

// ---------------------------------------------------------------------------
// Launch
// ---------------------------------------------------------------------------
extern "C" void kernel_launch(void* const* d_in, const int* in_sizes, int n_in,
                              void* d_out, int out_size) {
    const float* emission    = (const float*)d_in[0];
    const int*   target      = (const int*)  d_in[1];
    const float* mask        = (const float*)d_in[2];
    const float* start_trans = (const float*)d_in[3];
    const float* trans       = (const float*)d_in[4];
    float* out = (float*)d_out;

    crf_forward<<<64, 128>>>(emission, mask, start_trans, trans);
    crf_path<<<BB, 128>>>(emission, target, mask, start_trans, trans);
    crf_final<<<1, 512>>>(out);
}